// round 1
// baseline (speedup 1.0000x reference)
#include <cuda_runtime.h>
#include <math.h>

// ---------------- problem dims ----------------
#define NB   512      // batch
#define NT   128      // MAXLEN
#define NHE  512      // encoder hidden
#define NGE  2048     // 4*NHE
#define NZ   128      // latent
#define NHD  2048     // decoder hidden
#define NGD  8192     // 4*NHD
#define NOUTD 123     // 6*K+3
#define DLD  133      // dec_Wih leading dim (5+Z)
#define DATALD 129    // data: [B][129][2]

// ---------------- device scratch (no allocations allowed) ----------------
__device__ float g_hn  [NB * 2 * NHE];        // [b][dir*NHE + j]  (= concat(hF,hB))
__device__ float g_ce  [2 * NB * NHE];        // encoder cell state per dir
__device__ float g_Ge  [2 * NB * NGE];        // encoder gate preacts (GEMM out)
__device__ float g_zml [NB * 2 * NZ];         // [zm | zl]
__device__ float g_z   [NB * NZ];
__device__ float g_init[NB * 2 * NHD];
__device__ float g_hd  [NB * NHD];
__device__ float g_cd  [NB * NHD];
__device__ float g_zp  [NB * NGD];            // z-part of decoder input proj (+dec_b)
__device__ float g_G   [NB * NGD];            // decoder gate preacts (GEMM out)
__device__ float g_hs  [NB * NT * NHD];       // all decoder h (536 MB)

__device__ __forceinline__ float sigf(float x) { return 1.0f / (1.0f + expf(-x)); }

// ---------------- packed f32x2 helpers (Blackwell FFMA2 path) ----------------
__device__ __forceinline__ unsigned long long pk2(float x, float y) {
  unsigned long long r;
  asm("mov.b64 %0, {%1, %2};" : "=l"(r) : "f"(x), "f"(y));
  return r;
}
__device__ __forceinline__ void upk2(unsigned long long v, float &x, float &y) {
  asm("mov.b64 {%0, %1}, %2;" : "=f"(x), "=f"(y) : "l"(v));
}
__device__ __forceinline__ void fma2(unsigned long long &d, unsigned long long a,
                                     unsigned long long b) {
  asm("fma.rn.f32x2 %0, %1, %2, %0;" : "+l"(d) : "l"(a), "l"(b));
}

// ---------------- generic TN GEMM: C[m,n] = sum_k A[m,k]*W[n,k] (+bias[n]) ----
// A row-major [M,K] lda, W row-major [N,K] ldw. M must be multiple of 128,
// K multiple of 16. N arbitrary (guarded).
#define BM 128
#define BN 64
#define BK 16

__global__ __launch_bounds__(256) void gemm_tn(
    const float* __restrict__ A, int lda,
    const float* __restrict__ W, int ldw,
    const float* __restrict__ bias,
    float* __restrict__ C, int ldc,
    int N, int K)
{
  __shared__ float As[BK][BM];
  __shared__ float Ws[BK][BN];
  const int tid = threadIdx.x;
  const int tx = tid & 15;        // 16 threads over N (4 each)
  const int ty = tid >> 4;        // 16 threads over M (8 each)
  const int m0 = blockIdx.y * BM;
  const int n0 = blockIdx.x * BN;
  const int r  = tid >> 2;        // 0..63
  const int kg = (tid & 3) << 2;  // 0,4,8,12

  unsigned long long acc[4][4];
#pragma unroll
  for (int i = 0; i < 4; i++)
#pragma unroll
    for (int j = 0; j < 4; j++) acc[i][j] = 0ULL;

  const int  wr  = n0 + r;
  const bool wok = (wr < N);
  const float* ap0 = A + (size_t)(m0 + r) * lda + kg;
  const float* ap1 = A + (size_t)(m0 + r + 64) * lda + kg;
  const float* wp  = W + (size_t)(wok ? wr : 0) * ldw + kg;

  for (int k0 = 0; k0 < K; k0 += BK) {
    float4 v0 = *(const float4*)(ap0 + k0);
    float4 v1 = *(const float4*)(ap1 + k0);
    float w0 = 0.f, w1 = 0.f, w2 = 0.f, w3 = 0.f;
    if (wok) { w0 = wp[k0]; w1 = wp[k0 + 1]; w2 = wp[k0 + 2]; w3 = wp[k0 + 3]; }
    __syncthreads();
    As[kg + 0][r] = v0.x; As[kg + 1][r] = v0.y; As[kg + 2][r] = v0.z; As[kg + 3][r] = v0.w;
    As[kg + 0][r + 64] = v1.x; As[kg + 1][r + 64] = v1.y;
    As[kg + 2][r + 64] = v1.z; As[kg + 3][r + 64] = v1.w;
    Ws[kg + 0][r] = w0; Ws[kg + 1][r] = w1; Ws[kg + 2][r] = w2; Ws[kg + 3][r] = w3;
    __syncthreads();
#pragma unroll
    for (int k = 0; k < BK; k++) {
      float4 wv = *(const float4*)(&Ws[k][tx << 2]);
      unsigned long long wd0 = pk2(wv.x, wv.x);
      unsigned long long wd1 = pk2(wv.y, wv.y);
      unsigned long long wd2 = pk2(wv.z, wv.z);
      unsigned long long wd3 = pk2(wv.w, wv.w);
      const unsigned long long* ar =
          (const unsigned long long*)(&As[k][ty << 3]);  // 4x f32-pairs over M
#pragma unroll
      for (int i = 0; i < 4; i++) {
        unsigned long long a2 = ar[i];
        fma2(acc[i][0], a2, wd0);
        fma2(acc[i][1], a2, wd1);
        fma2(acc[i][2], a2, wd2);
        fma2(acc[i][3], a2, wd3);
      }
    }
  }

#pragma unroll
  for (int i = 0; i < 4; i++) {
    int m = m0 + (ty << 3) + 2 * i;
#pragma unroll
    for (int j = 0; j < 4; j++) {
      int n = n0 + (tx << 2) + j;
      if (n < N) {
        float x, y;
        upk2(acc[i][j], x, y);
        float bb = bias ? bias[n] : 0.0f;
        C[(size_t)m * ldc + n]       = x + bb;
        C[(size_t)(m + 1) * ldc + n] = y + bb;
      }
    }
  }
}

// ---------------- elementwise kernels ----------------
__global__ void zero_init_kernel() {
  int idx = blockIdx.x * blockDim.x + threadIdx.x;  // 524288 threads
  if (idx < NB * 2 * NHE) { g_hn[idx] = 0.0f; g_ce[idx] = 0.0f; }
}

__global__ void enc_gate_kernel(const float* __restrict__ data,
                                const int* __restrict__ lengths,
                                const float* __restrict__ Wih_f,
                                const float* __restrict__ Wih_b, int t) {
  int idx = blockIdx.x * blockDim.x + threadIdx.x;   // 2*512*512
  int dir = idx >> 18;
  int rr  = idx & ((1 << 18) - 1);
  int b = rr >> 9;
  int j = rr & 511;
  int L = lengths[b];
  L = L < 1 ? 1 : (L > NT ? NT : L);
  if (t >= L) return;                                // masked step: h,c unchanged
  int ti = dir ? (L - 1 - t) : t;
  float x0 = data[((size_t)b * DATALD + ti + 1) * 2 + 0];
  float x1 = data[((size_t)b * DATALD + ti + 1) * 2 + 1];
  const float* Wih = dir ? Wih_b : Wih_f;
  const float* G = g_Ge + (size_t)(dir * NB + b) * NGE;
  float pi = G[j]            + x0 * Wih[2 * j]                 + x1 * Wih[2 * j + 1];
  float pf = G[NHE + j]      + x0 * Wih[2 * (NHE + j)]         + x1 * Wih[2 * (NHE + j) + 1];
  float pg = G[2 * NHE + j]  + x0 * Wih[2 * (2 * NHE + j)]     + x1 * Wih[2 * (2 * NHE + j) + 1];
  float po = G[3 * NHE + j]  + x0 * Wih[2 * (3 * NHE + j)]     + x1 * Wih[2 * (3 * NHE + j) + 1];
  int ci = (dir * NB + b) * NHE + j;
  float c  = g_ce[ci];
  float c2 = sigf(pf) * c + sigf(pi) * tanhf(pg);
  float h2 = sigf(po) * tanhf(c2);
  g_ce[ci] = c2;
  g_hn[b * (2 * NHE) + dir * NHE + j] = h2;
}

__global__ void latent_kernel(const float* __restrict__ eps,
                              float* __restrict__ zm_out,
                              float* __restrict__ zl_out) {
  int idx = blockIdx.x * blockDim.x + threadIdx.x;   // 65536
  int b = idx >> 7, k = idx & 127;
  float zm = g_zml[b * 256 + k];
  float zl = g_zml[b * 256 + 128 + k];
  zm_out[idx] = zm;
  zl_out[idx] = zl;
  g_z[idx] = zm + expf(0.5f * zl) * eps[idx];
}

__global__ void initsplit_kernel() {
  int idx = blockIdx.x * blockDim.x + threadIdx.x;   // 512*2048
  int b = idx >> 11, j = idx & 2047;
  g_hd[idx] = tanhf(g_init[b * (2 * NHD) + j]);
  g_cd[idx] = tanhf(g_init[b * (2 * NHD) + NHD + j]);
}

__global__ void dec_gate_kernel(const float* __restrict__ data,
                                const float* __restrict__ Wih, int t) {
  int idx = blockIdx.x * blockDim.x + threadIdx.x;   // 512*2048
  int b = idx >> 11, j = idx & 2047;
  float x0 = data[((size_t)b * DATALD + t) * 2 + 0];
  float x1 = data[((size_t)b * DATALD + t) * 2 + 1];
  const float* G  = g_G  + (size_t)b * NGD;
  const float* Zp = g_zp + (size_t)b * NGD;
  int r0 = j, r1 = j + NHD, r2 = j + 2 * NHD, r3 = j + 3 * NHD;
  float pi = G[r0] + Zp[r0] + x0 * Wih[(size_t)r0 * DLD] + x1 * Wih[(size_t)r0 * DLD + 1];
  float pf = G[r1] + Zp[r1] + x0 * Wih[(size_t)r1 * DLD] + x1 * Wih[(size_t)r1 * DLD + 1];
  float pg = G[r2] + Zp[r2] + x0 * Wih[(size_t)r2 * DLD] + x1 * Wih[(size_t)r2 * DLD + 1];
  float po = G[r3] + Zp[r3] + x0 * Wih[(size_t)r3 * DLD] + x1 * Wih[(size_t)r3 * DLD + 1];
  float c  = g_cd[idx];
  float c2 = sigf(pf) * c + sigf(pi) * tanhf(pg);
  float h2 = sigf(po) * tanhf(c2);
  g_cd[idx] = c2;
  g_hd[idx] = h2;
  g_hs[((size_t)b * NT + t) * NHD + j] = h2;
}

// ---------------- launch ----------------
extern "C" void kernel_launch(void* const* d_in, const int* in_sizes, int n_in,
                              void* d_out, int out_size) {
  const float* data      = (const float*)d_in[0];
  const float* eps       = (const float*)d_in[1];
  const float* enc_Wih_f = (const float*)d_in[2];
  const float* enc_Whh_f = (const float*)d_in[3];
  const float* enc_b_f   = (const float*)d_in[4];
  const float* enc_Wih_b = (const float*)d_in[5];
  const float* enc_Whh_b = (const float*)d_in[6];
  const float* enc_b_b   = (const float*)d_in[7];
  const float* enc_out_W = (const float*)d_in[8];
  const float* enc_out_b = (const float*)d_in[9];
  const float* init_W    = (const float*)d_in[10];
  const float* init_b    = (const float*)d_in[11];
  const float* dec_Wih   = (const float*)d_in[12];
  const float* dec_Whh   = (const float*)d_in[13];
  const float* dec_b     = (const float*)d_in[14];
  const float* out_W     = (const float*)d_in[15];
  const float* out_b     = (const float*)d_in[16];
  const int*   lengths   = (const int*)d_in[17];

  float* out    = (float*)d_out;
  float* params = out;                                    // [512,128,123]
  float* zm_out = out + (size_t)NB * NT * NOUTD;          // [512,128]
  float* zl_out = zm_out + (size_t)NB * NT;               // [512,128]

  float *p_hn, *p_Ge, *p_zml, *p_z, *p_init, *p_zp, *p_hd, *p_G, *p_hs;
  cudaGetSymbolAddress((void**)&p_hn,  g_hn);
  cudaGetSymbolAddress((void**)&p_Ge,  g_Ge);
  cudaGetSymbolAddress((void**)&p_zml, g_zml);
  cudaGetSymbolAddress((void**)&p_z,   g_z);
  cudaGetSymbolAddress((void**)&p_init,g_init);
  cudaGetSymbolAddress((void**)&p_zp,  g_zp);
  cudaGetSymbolAddress((void**)&p_hd,  g_hd);
  cudaGetSymbolAddress((void**)&p_G,   g_G);
  cudaGetSymbolAddress((void**)&p_hs,  g_hs);

  zero_init_kernel<<<2048, 256>>>();

  // ---- bidirectional encoder, 128 steps ----
  dim3 gEnc(NGE / BN, NB / BM);  // (32, 4)
  for (int t = 0; t < NT; t++) {
    gemm_tn<<<gEnc, 256>>>(p_hn,       2 * NHE, enc_Whh_f, NHE, enc_b_f,
                           p_Ge,            NGE, NGE, NHE);
    gemm_tn<<<gEnc, 256>>>(p_hn + NHE, 2 * NHE, enc_Whh_b, NHE, enc_b_b,
                           p_Ge + NB * NGE, NGE, NGE, NHE);
    enc_gate_kernel<<<2048, 256>>>(data, lengths, enc_Wih_f, enc_Wih_b, t);
  }

  // ---- latent ----
  gemm_tn<<<dim3(2 * NZ / BN, NB / BM), 256>>>(p_hn, 2 * NHE, enc_out_W, 2 * NHE,
                                               enc_out_b, p_zml, 2 * NZ, 2 * NZ, 2 * NHE);
  latent_kernel<<<256, 256>>>(eps, zm_out, zl_out);
  gemm_tn<<<dim3(2 * NHD / BN, NB / BM), 256>>>(p_z, NZ, init_W, NZ, init_b,
                                                p_init, 2 * NHD, 2 * NHD, NZ);
  initsplit_kernel<<<4096, 256>>>();
  // z-part of decoder input projection (+dec_b), cols 5..132 of dec_Wih
  gemm_tn<<<dim3(NGD / BN, NB / BM), 256>>>(p_z, NZ, dec_Wih + 5, DLD, dec_b,
                                            p_zp, NGD, NGD, NZ);

  // ---- decoder, 128 steps ----
  dim3 gDec(NGD / BN, NB / BM);  // (128, 4)
  for (int t = 0; t < NT; t++) {
    gemm_tn<<<gDec, 256>>>(p_hd, NHD, dec_Whh, NHD, (const float*)nullptr,
                           p_G, NGD, NGD, NHD);
    dec_gate_kernel<<<4096, 256>>>(data, dec_Wih, t);
  }

  // ---- output projection over all stored h ----
  gemm_tn<<<dim3((NOUTD + BN - 1) / BN, (NB * NT) / BM), 256>>>(
      p_hs, NHD, out_W, NHD, out_b, params, NOUTD, NOUTD, NHD);
}

// round 3
// speedup vs baseline: 4.0759x; 4.0759x over previous
#include <cuda_runtime.h>
#include <cuda_bf16.h>
#include <math.h>
#include <stdint.h>

#define NB 512
#define NT 128
#define NHE 512
#define NGE 2048
#define NZ 128
#define NHD 2048
#define NGD 8192
#define NOUTD 123
#define DATALD 129
#define DLD 133

// Use tcgen05 only when the compilation target is arch-specific sm_103a/100a.
#if !defined(__CUDA_ARCH__)
#define USE_TC 1   // host pass: pick either branch (no device codegen)
#elif defined(__CUDA_ARCH_FEAT_SM103_ALL) || defined(__CUDA_ARCH_FEAT_SM100_ALL)
#define USE_TC 1
#else
#define USE_TC 0
#endif

// ---------------- device scratch (statics; no runtime allocation) ----------------
__device__ __nv_bfloat16 g_dWhh_hi[NGD * NHD];
__device__ __nv_bfloat16 g_dWhh_lo[NGD * NHD];
__device__ __nv_bfloat16 g_eWf_hi[NGE * NHE];
__device__ __nv_bfloat16 g_eWf_lo[NGE * NHE];
__device__ __nv_bfloat16 g_eWb_hi[NGE * NHE];
__device__ __nv_bfloat16 g_eWb_lo[NGE * NHE];
__device__ __nv_bfloat16 g_eOut_hi[2 * NZ * 2 * NHE];
__device__ __nv_bfloat16 g_eOut_lo[2 * NZ * 2 * NHE];
__device__ __nv_bfloat16 g_initW_hi[2 * NHD * NZ];
__device__ __nv_bfloat16 g_initW_lo[2 * NHD * NZ];
__device__ __nv_bfloat16 g_zW_hi[NGD * NZ];
__device__ __nv_bfloat16 g_zW_lo[NGD * NZ];
__device__ __nv_bfloat16 g_outW_hi[NOUTD * NHD];
__device__ __nv_bfloat16 g_outW_lo[NOUTD * NHD];

__device__ __nv_bfloat16 g_hn_hi[NB * 2 * NHE];
__device__ __nv_bfloat16 g_hn_lo[NB * 2 * NHE];
__device__ float g_ce[2 * NB * NHE];
__device__ float g_Ge[2 * NB * NGE];
__device__ float g_zml[NB * 2 * NZ];
__device__ __nv_bfloat16 g_z_hi[NB * NZ];
__device__ __nv_bfloat16 g_z_lo[NB * NZ];
__device__ float g_init[NB * 2 * NHD];
__device__ __nv_bfloat16 g_h0_hi[NB * NHD];
__device__ __nv_bfloat16 g_h0_lo[NB * NHD];
__device__ float g_cd[NB * NHD];
__device__ float g_zp[NB * NGD];
__device__ float g_G[NB * NGD];
__device__ __nv_bfloat16 g_hs_hi[(size_t)NB * NT * NHD];
__device__ __nv_bfloat16 g_hs_lo[(size_t)NB * NT * NHD];

// ---------------- common helpers ----------------
__device__ __forceinline__ uint32_t smem_u32(const void* p) {
  uint32_t a;
  asm("{ .reg .u64 t; cvta.to.shared.u64 t, %1; cvt.u32.u64 %0, t; }" : "=r"(a) : "l"(p));
  return a;
}
__device__ __forceinline__ void cp16(uint32_t dst, const void* src, bool ok) {
  int sz = ok ? 16 : 0;
  asm volatile("cp.async.cg.shared.global [%0], [%1], 16, %2;\n"
               :: "r"(dst), "l"(src), "r"(sz) : "memory");
}
__device__ __forceinline__ void cp_commit() { asm volatile("cp.async.commit_group;" ::: "memory"); }
__device__ __forceinline__ void cp_wait1()  { asm volatile("cp.async.wait_group 1;" ::: "memory"); }
__device__ __forceinline__ void cp_wait0()  { asm volatile("cp.async.wait_group 0;" ::: "memory"); }

struct GArg {
  const __nv_bfloat16 *Ahi, *Alo;      // [M][K] fp32-split, row stride lda
  const __nv_bfloat16 *Whi, *Wlo;      // [N][K] packed (ldw == K)
  const float *bias;                   // [N] or null
  const float *Cadd;                   // [M][ldc] addend or null
  float *C;                            // [M][ldc]
};

#define STAGE_BYTES 98304u
#define GSMEM (1024u + 2u * STAGE_BYTES)

#if USE_TC
// =====================================================================
// tcgen05 path (only compiled for sm_103a/100a arch-specific targets)
// =====================================================================
__device__ __forceinline__ uint32_t elect_one_pred() {
  uint32_t pred;
  asm volatile(
      "{\n\t.reg .pred p;\n\telect.sync _|p, 0xFFFFFFFF;\n\tselp.b32 %0, 1, 0, p;\n\t}"
      : "=r"(pred));
  return pred;
}
#define MBARRIER_INIT(addr, cnt) \
  asm volatile("mbarrier.init.shared.b64 [%0], %1;" :: "r"((uint32_t)(addr)), "r"((uint32_t)(cnt)) : "memory")
#define MBARRIER_WAIT_PARITY(addr, par) do {                                        \
  uint32_t _m = (uint32_t)(addr); uint32_t _p = (uint32_t)(par); uint32_t _d;       \
  asm volatile("{\n\t.reg .pred p;\n\t"                                             \
    "mbarrier.try_wait.parity.acquire.cta.shared::cta.b64 p, [%1], %2;\n\t"         \
    "selp.b32 %0, 1, 0, p;\n\t}" : "=r"(_d) : "r"(_m), "r"(_p) : "memory");         \
  if (!_d) {                                                                        \
    asm volatile("{\n\t.reg .pred P1;\n\t"                                          \
      "WL_%=:\n\t"                                                                  \
      "mbarrier.try_wait.parity.acquire.cta.shared::cta.b64 P1, [%0], %1, 0x989680;\n\t" \
      "@P1 bra.uni WD_%=;\n\t"                                                      \
      "bra.uni WL_%=;\n\t"                                                          \
      "WD_%=:\n\t}" :: "r"(_m), "r"(_p) : "memory");                                \
  }                                                                                 \
} while (0)

#define TCGEN05_ALLOC(sm, n) \
  asm volatile("tcgen05.alloc.cta_group::1.sync.aligned.shared::cta.b32 [%0], %1;" \
               :: "r"((uint32_t)(sm)), "r"((uint32_t)(n)) : "memory")
#define TCGEN05_DEALLOC(t, n) \
  asm volatile("tcgen05.dealloc.cta_group::1.sync.aligned.b32 %0, %1;" :: "r"(t), "r"((uint32_t)(n)))
#define TCGEN05_RELINQ() \
  asm volatile("tcgen05.relinquish_alloc_permit.cta_group::1.sync.aligned;")
#define TCGEN05_COMMIT(mb) \
  asm volatile("tcgen05.commit.cta_group::1.mbarrier::arrive::one.shared::cluster.b64 [%0];" \
               :: "r"((uint32_t)(mb)) : "memory")
#define TCGEN05_FENCE_AFTER()  asm volatile("tcgen05.fence::after_thread_sync;" ::: "memory")
#define TCGEN05_FENCE_BEFORE() asm volatile("tcgen05.fence::before_thread_sync;" ::: "memory")
#define TCGEN05_WAIT_LD()      asm volatile("tcgen05.wait::ld.sync.aligned;" ::: "memory")

#define TCGEN05_LD_32X32B_X32(r, addr)                                            \
  asm volatile(                                                                   \
      "tcgen05.ld.sync.aligned.32x32b.x32.b32 "                                   \
      "{%0, %1, %2, %3, %4, %5, %6, %7, %8, %9, %10, %11, %12, %13, %14, %15, "   \
      " %16, %17, %18, %19, %20, %21, %22, %23, %24, %25, %26, %27, %28, %29, %30, %31}, [%32];" \
      : "=r"((r)[0]), "=r"((r)[1]), "=r"((r)[2]), "=r"((r)[3]),                   \
        "=r"((r)[4]), "=r"((r)[5]), "=r"((r)[6]), "=r"((r)[7]),                   \
        "=r"((r)[8]), "=r"((r)[9]), "=r"((r)[10]), "=r"((r)[11]),                 \
        "=r"((r)[12]), "=r"((r)[13]), "=r"((r)[14]), "=r"((r)[15]),               \
        "=r"((r)[16]), "=r"((r)[17]), "=r"((r)[18]), "=r"((r)[19]),               \
        "=r"((r)[20]), "=r"((r)[21]), "=r"((r)[22]), "=r"((r)[23]),               \
        "=r"((r)[24]), "=r"((r)[25]), "=r"((r)[26]), "=r"((r)[27]),               \
        "=r"((r)[28]), "=r"((r)[29]), "=r"((r)[30]), "=r"((r)[31])                \
      : "r"(addr))

static constexpr unsigned long long SMEM_DESC_BASE_SW128 =
    (2ull << 61) | (1ull << 46) | (64ull << 32) | (1ull << 16);
#define MAKE_SMEM_DESC(a) (SMEM_DESC_BASE_SW128 | ((unsigned long long)((a) >> 4) & 0x3FFF))

static constexpr uint32_t IDESC =
    (1u << 4) | (1u << 7) | (1u << 10) | ((256u / 8u) << 17) | ((128u / 16u) << 24);

__device__ __forceinline__ void mma_ss(uint32_t d, unsigned long long a,
                                       unsigned long long b, uint32_t en) {
  asm volatile(
      "{\n\t.reg .pred p;\n\tsetp.ne.u32 p, %4, 0;\n\t"
      "tcgen05.mma.cta_group::1.kind::f16 [%0], %1, %2, %3, {%5, %5, %5, %5}, p;\n\t}"
      :: "r"(d), "l"(a), "l"(b), "r"(IDESC), "r"(en), "r"(0u) : "memory");
}

__device__ __forceinline__ void load_stage(
    uint32_t sb, int stage, int ci, const GArg& g, size_t lda,
    int m0, int n0, int N, int K, int tid)
{
  const uint32_t base = sb + 1024u + (uint32_t)stage * STAGE_BYTES;
  const int k0 = ci << 6;
#pragma unroll
  for (int it = 0; it < 4; ++it) {
    int idx = tid + (it << 8);
    int row = idx >> 3, c = idx & 7;
    uint32_t off = (uint32_t)((row << 7) + (c << 4));
    off ^= ((off >> 3) & 0x70);
    size_t so = (size_t)(m0 + row) * lda + (size_t)k0 + (c << 3);
    cp16(base + off, g.Ahi + so, true);
    cp16(base + 16384u + off, g.Alo + so, true);
  }
#pragma unroll
  for (int it = 0; it < 8; ++it) {
    int idx = tid + (it << 8);
    int row = idx >> 3, c = idx & 7;
    int n = n0 + row;
    bool ok = (n < N);
    size_t so = (size_t)(ok ? n : 0) * (size_t)K + (size_t)k0 + (c << 3);
    uint32_t off = (uint32_t)((row << 7) + (c << 4));
    off ^= ((off >> 3) & 0x70);
    cp16(base + 32768u + off, g.Whi + so, ok);
    cp16(base + 65536u + off, g.Wlo + so, ok);
  }
  cp_commit();
}

__device__ __forceinline__ void mma_chunk(uint32_t sb, int stage, uint32_t tmem, bool first) {
  uint32_t base = sb + 1024u + (uint32_t)stage * STAGE_BYTES;
  unsigned long long dAh = MAKE_SMEM_DESC(base);
  unsigned long long dAl = MAKE_SMEM_DESC(base + 16384u);
  unsigned long long dBh = MAKE_SMEM_DESC(base + 32768u);
  unsigned long long dBl = MAKE_SMEM_DESC(base + 65536u);
#pragma unroll
  for (int ks = 0; ks < 4; ++ks) {
    unsigned long long o = (unsigned long long)(2 * ks);
    mma_ss(tmem, dAh + o, dBh + o, (first && ks == 0) ? 0u : 1u);
    mma_ss(tmem, dAh + o, dBl + o, 1u);
    mma_ss(tmem, dAl + o, dBh + o, 1u);
  }
}

__global__ void __launch_bounds__(256, 1) gemm3(GArg a0, GArg a1, size_t lda,
                                                size_t ldc, int N, int K) {
  extern __shared__ __align__(1024) char smem[];
  const int tid = threadIdx.x;
  const uint32_t sb = smem_u32(smem);
  const GArg g = blockIdx.z ? a1 : a0;
  const int m0 = blockIdx.y * 128;
  const int n0 = blockIdx.x * 256;

  if (tid == 0) { MBARRIER_INIT(sb + 16, 1); MBARRIER_INIT(sb + 24, 1); }
  if (tid < 32) TCGEN05_ALLOC(sb, 256);
  __syncthreads();
  uint32_t tmem;
  asm volatile("ld.shared.b32 %0, [%1];" : "=r"(tmem) : "r"(sb));

  const int nch = K >> 6;
  load_stage(sb, 0, 0, g, lda, m0, n0, N, K, tid);
  load_stage(sb, 1, 1, g, lda, m0, n0, N, K, tid);

  for (int i = 0; i < nch; ++i) {
    const int b = i & 1;
    if (i + 1 < nch) cp_wait1(); else cp_wait0();
    asm volatile("fence.proxy.async.shared::cta;" ::: "memory");
    __syncthreads();
    if (tid < 32) {
      if (elect_one_pred()) {
        mma_chunk(sb, b, tmem, i == 0);
        TCGEN05_COMMIT(sb + 16 + 8 * b);
      }
    }
    if (i + 2 < nch) {
      MBARRIER_WAIT_PARITY(sb + 16 + 8 * b, (i >> 1) & 1);
      load_stage(sb, b, i + 2, g, lda, m0, n0, N, K, tid);
    }
  }
  const int last = nch - 1;
  MBARRIER_WAIT_PARITY(sb + 16 + 8 * (last & 1), (last >> 1) & 1);
  TCGEN05_FENCE_AFTER();

  if (tid < 128) {
    const int w = tid >> 5, lane = tid & 31;
    const size_t m = (size_t)m0 + (size_t)(w * 32 + lane);
    float* crow = g.C + m * ldc;
    const float* arow = g.Cadd ? (g.Cadd + m * ldc) : (const float*)0;
    for (int c0 = 0; c0 < 256; c0 += 32) {
      int n = n0 + c0;
      if (n >= N) break;
      uint32_t r[32];
      TCGEN05_LD_32X32B_X32(r, tmem + c0);
      TCGEN05_WAIT_LD();
      if (((ldc & 3) == 0) && (n + 32 <= N)) {
#pragma unroll
        for (int q = 0; q < 8; ++q) {
          float4 v;
          v.x = __uint_as_float(r[4 * q + 0]);
          v.y = __uint_as_float(r[4 * q + 1]);
          v.z = __uint_as_float(r[4 * q + 2]);
          v.w = __uint_as_float(r[4 * q + 3]);
          if (g.bias) {
            float4 bv = *(const float4*)(g.bias + n + 4 * q);
            v.x += bv.x; v.y += bv.y; v.z += bv.z; v.w += bv.w;
          }
          if (arow) {
            float4 av = *(const float4*)(arow + n + 4 * q);
            v.x += av.x; v.y += av.y; v.z += av.z; v.w += av.w;
          }
          *(float4*)(crow + n + 4 * q) = v;
        }
      } else {
        for (int j = 0; j < 32 && n + j < N; ++j) {
          float v = __uint_as_float(r[j]);
          if (g.bias) v += g.bias[n + j];
          if (arow) v += arow[n + j];
          crow[n + j] = v;
        }
      }
    }
    TCGEN05_FENCE_BEFORE();
  }
  __syncthreads();
  if (tid < 32) { TCGEN05_RELINQ(); TCGEN05_DEALLOC(tmem, 256); }
}

#else
// =====================================================================
// Fallback path: mma.sync.m16n8k16 bf16 (baseline PTX, works on sm_103)
// CTA tile 128x256 processed as two 128x128 halves. hi/lo 3-term split.
// =====================================================================
#define KC 64
#define FSTAGE 65536u

__device__ __forceinline__ uint32_t lds_sw(uint32_t mat, int row, int kelem) {
  uint32_t off = (uint32_t)((row << 7) + (kelem << 1));
  off ^= (off >> 3) & 0x70;
  uint32_t v;
  asm volatile("ld.shared.b32 %0, [%1];" : "=r"(v) : "r"(mat + off));
  return v;
}
__device__ __forceinline__ void mma16816(float* c, uint32_t a0, uint32_t a1,
                                         uint32_t a2, uint32_t a3,
                                         uint32_t b0, uint32_t b1) {
  asm volatile(
      "mma.sync.aligned.m16n8k16.row.col.f32.bf16.bf16.f32 "
      "{%0,%1,%2,%3}, {%4,%5,%6,%7}, {%8,%9}, {%0,%1,%2,%3};"
      : "+f"(c[0]), "+f"(c[1]), "+f"(c[2]), "+f"(c[3])
      : "r"(a0), "r"(a1), "r"(a2), "r"(a3), "r"(b0), "r"(b1));
}

__device__ __forceinline__ void f_load_stage(
    uint32_t sb, int stage, int ci, int hf, const GArg& g, size_t lda,
    int m0, int n0, int N, int K, int tid)
{
  const uint32_t base = sb + (uint32_t)stage * FSTAGE;
  const int k0 = ci * KC;
#pragma unroll
  for (int it = 0; it < 4; ++it) {
    int idx = tid + (it << 8);
    int row = idx >> 3, c = idx & 7;
    uint32_t off = (uint32_t)((row << 7) + (c << 4));
    off ^= (off >> 3) & 0x70;
    size_t soA = (size_t)(m0 + row) * lda + (size_t)k0 + (c << 3);
    cp16(base + off, g.Ahi + soA, true);
    cp16(base + 16384u + off, g.Alo + soA, true);
    int n = n0 + hf * 128 + row;
    bool ok = (n < N);
    size_t soB = (size_t)(ok ? n : 0) * (size_t)K + (size_t)k0 + (c << 3);
    cp16(base + 32768u + off, g.Whi + soB, ok);
    cp16(base + 49152u + off, g.Wlo + soB, ok);
  }
  cp_commit();
}

__global__ void __launch_bounds__(256, 1) gemm3(GArg a0, GArg a1, size_t lda,
                                                size_t ldc, int N, int K) {
  extern __shared__ __align__(1024) char smem[];
  const int tid = threadIdx.x;
  const uint32_t sb = smem_u32(smem);
  const GArg g = blockIdx.z ? a1 : a0;
  const int m0 = blockIdx.y * 128;
  const int n0 = blockIdx.x * 256;
  const int w = tid >> 5, l = tid & 31;
  const int r = l >> 2, c2 = (l & 3) << 1;
  const int nch = K / KC;

  for (int hf = 0; hf < 2; ++hf) {
    if (n0 + hf * 128 >= N) break;
    float acc[16][4];
#pragma unroll
    for (int i = 0; i < 16; ++i)
#pragma unroll
      for (int j = 0; j < 4; ++j) acc[i][j] = 0.0f;

    f_load_stage(sb, 0, 0, hf, g, lda, m0, n0, N, K, tid);
    f_load_stage(sb, 1, 1, hf, g, lda, m0, n0, N, K, tid);

    for (int ci = 0; ci < nch; ++ci) {
      const int b = ci & 1;
      if (ci + 1 < nch) cp_wait1(); else cp_wait0();
      __syncthreads();
      const uint32_t Ah = sb + (uint32_t)b * FSTAGE;
      const uint32_t Al = Ah + 16384u;
      const uint32_t Bh = Ah + 32768u;
      const uint32_t Bl = Ah + 49152u;
      const int mrow = w * 16 + r;
#pragma unroll
      for (int ks = 0; ks < 4; ++ks) {
        const int kb = ks * 16;
        uint32_t ah0 = lds_sw(Ah, mrow,     kb + c2);
        uint32_t ah1 = lds_sw(Ah, mrow + 8, kb + c2);
        uint32_t ah2 = lds_sw(Ah, mrow,     kb + c2 + 8);
        uint32_t ah3 = lds_sw(Ah, mrow + 8, kb + c2 + 8);
        uint32_t al0 = lds_sw(Al, mrow,     kb + c2);
        uint32_t al1 = lds_sw(Al, mrow + 8, kb + c2);
        uint32_t al2 = lds_sw(Al, mrow,     kb + c2 + 8);
        uint32_t al3 = lds_sw(Al, mrow + 8, kb + c2 + 8);
#pragma unroll
        for (int nb = 0; nb < 16; ++nb) {
          const int nr = nb * 8 + r;
          uint32_t bh0 = lds_sw(Bh, nr, kb + c2);
          uint32_t bh1 = lds_sw(Bh, nr, kb + c2 + 8);
          uint32_t bl0 = lds_sw(Bl, nr, kb + c2);
          uint32_t bl1 = lds_sw(Bl, nr, kb + c2 + 8);
          mma16816(acc[nb], ah0, ah1, ah2, ah3, bh0, bh1);
          mma16816(acc[nb], ah0, ah1, ah2, ah3, bl0, bl1);
          mma16816(acc[nb], al0, al1, al2, al3, bh0, bh1);
        }
      }
      __syncthreads();
      if (ci + 2 < nch) f_load_stage(sb, b, ci + 2, hf, g, lda, m0, n0, N, K, tid);
    }

    // epilogue for this half
    const int mtop = m0 + w * 16 + r;
#pragma unroll
    for (int nb = 0; nb < 16; ++nb) {
      int n = n0 + hf * 128 + nb * 8 + c2;
#pragma unroll
      for (int half = 0; half < 2; ++half) {
        int m = mtop + half * 8;
        float v0 = acc[nb][2 * half], v1 = acc[nb][2 * half + 1];
        if (g.bias) { v0 += g.bias[n < N ? n : 0]; v1 += (n + 1 < N) ? g.bias[n + 1] : 0.0f; }
        if (g.Cadd) {
          const float* arow = g.Cadd + (size_t)m * ldc;
          if (n < N) v0 += arow[n];
          if (n + 1 < N) v1 += arow[n + 1];
        }
        float* crow = g.C + (size_t)m * ldc;
        if (n < N) crow[n] = v0;
        if (n + 1 < N) crow[n + 1] = v1;
      }
    }
  }
}
#endif  // USE_TC

// ---------------- small kernels ----------------
__device__ __forceinline__ float sigf(float x) { return 1.0f / (1.0f + expf(-x)); }
__device__ __forceinline__ void split_bf16(float x, __nv_bfloat16* hi, __nv_bfloat16* lo) {
  __nv_bfloat16 h = __float2bfloat16(x);
  *hi = h;
  *lo = __float2bfloat16(x - __bfloat162float(h));
}

__global__ void cvt_kernel(const float* __restrict__ src, long ld, int K,
                           __nv_bfloat16* __restrict__ hi, __nv_bfloat16* __restrict__ lo,
                           long total) {
  long idx = blockIdx.x * (long)blockDim.x + threadIdx.x;
  if (idx >= total) return;
  float x;
  if (ld == K) x = src[idx];
  else {
    long n = idx / K, k = idx - n * K;
    x = src[n * ld + k];
  }
  split_bf16(x, hi + idx, lo + idx);
}

__global__ void zero_init_kernel() {
  int idx = blockIdx.x * blockDim.x + threadIdx.x;
  g_hn_hi[idx] = __float2bfloat16(0.0f);
  g_hn_lo[idx] = __float2bfloat16(0.0f);
  g_ce[idx] = 0.0f;
}

__global__ void enc_gate_kernel(const float* __restrict__ data,
                                const int* __restrict__ lengths,
                                const float* __restrict__ Wih_f,
                                const float* __restrict__ Wih_b, int t) {
  int idx = blockIdx.x * blockDim.x + threadIdx.x;
  int dir = idx >> 18;
  int rr = idx & ((1 << 18) - 1);
  int b = rr >> 9;
  int j = rr & 511;
  int L = lengths[b];
  L = L < 1 ? 1 : (L > NT ? NT : L);
  if (t >= L) return;
  int ti = dir ? (L - 1 - t) : t;
  float x0 = data[((size_t)b * DATALD + ti + 1) * 2 + 0];
  float x1 = data[((size_t)b * DATALD + ti + 1) * 2 + 1];
  const float* Wih = dir ? Wih_b : Wih_f;
  const float* G = g_Ge + (size_t)(dir * NB + b) * NGE;
  float pi = G[j]           + x0 * Wih[2 * j]               + x1 * Wih[2 * j + 1];
  float pf = G[NHE + j]     + x0 * Wih[2 * (NHE + j)]       + x1 * Wih[2 * (NHE + j) + 1];
  float pg = G[2 * NHE + j] + x0 * Wih[2 * (2 * NHE + j)]   + x1 * Wih[2 * (2 * NHE + j) + 1];
  float po = G[3 * NHE + j] + x0 * Wih[2 * (3 * NHE + j)]   + x1 * Wih[2 * (3 * NHE + j) + 1];
  int ci = (dir * NB + b) * NHE + j;
  float c = g_ce[ci];
  float c2 = sigf(pf) * c + sigf(pi) * tanhf(pg);
  float h2 = sigf(po) * tanhf(c2);
  g_ce[ci] = c2;
  int hidx = b * (2 * NHE) + dir * NHE + j;
  split_bf16(h2, &g_hn_hi[hidx], &g_hn_lo[hidx]);
}

__global__ void latent_kernel(const float* __restrict__ eps,
                              float* __restrict__ zm_out,
                              float* __restrict__ zl_out) {
  int idx = blockIdx.x * blockDim.x + threadIdx.x;
  int b = idx >> 7, k = idx & 127;
  float zm = g_zml[b * 256 + k];
  float zl = g_zml[b * 256 + 128 + k];
  zm_out[idx] = zm;
  zl_out[idx] = zl;
  float z = zm + expf(0.5f * zl) * eps[idx];
  split_bf16(z, &g_z_hi[idx], &g_z_lo[idx]);
}

__global__ void initsplit_kernel() {
  int idx = blockIdx.x * blockDim.x + threadIdx.x;
  int b = idx >> 11, j = idx & 2047;
  float h0 = tanhf(g_init[b * (2 * NHD) + j]);
  float c0 = tanhf(g_init[b * (2 * NHD) + NHD + j]);
  g_cd[idx] = c0;
  split_bf16(h0, &g_h0_hi[idx], &g_h0_lo[idx]);
}

__global__ void dec_gate_kernel(const float* __restrict__ data,
                                const float* __restrict__ Wih, int t) {
  int idx = blockIdx.x * blockDim.x + threadIdx.x;
  int b = idx >> 11, j = idx & 2047;
  float x0 = data[((size_t)b * DATALD + t) * 2 + 0];
  float x1 = data[((size_t)b * DATALD + t) * 2 + 1];
  const float* G = g_G + (size_t)b * NGD;
  int r0 = j, r1 = j + NHD, r2 = j + 2 * NHD, r3 = j + 3 * NHD;
  float pi = G[r0] + x0 * Wih[(size_t)r0 * DLD] + x1 * Wih[(size_t)r0 * DLD + 1];
  float pf = G[r1] + x0 * Wih[(size_t)r1 * DLD] + x1 * Wih[(size_t)r1 * DLD + 1];
  float pg = G[r2] + x0 * Wih[(size_t)r2 * DLD] + x1 * Wih[(size_t)r2 * DLD + 1];
  float po = G[r3] + x0 * Wih[(size_t)r3 * DLD] + x1 * Wih[(size_t)r3 * DLD + 1];
  float c = g_cd[idx];
  float c2 = sigf(pf) * c + sigf(pi) * tanhf(pg);
  float h2 = sigf(po) * tanhf(c2);
  g_cd[idx] = c2;
  size_t ho = ((size_t)b * NT + t) * NHD + j;
  split_bf16(h2, &g_hs_hi[ho], &g_hs_lo[ho]);
}

// ---------------- launch ----------------
static inline void run_gemm(GArg a0, GArg a1, size_t lda, size_t ldc, int N, int K,
                            int M, int nz) {
  dim3 grid((unsigned)((N + 255) / 256), (unsigned)(M / 128), (unsigned)nz);
  gemm3<<<grid, 256, GSMEM>>>(a0, a1, lda, ldc, N, K);
}

extern "C" void kernel_launch(void* const* d_in, const int* in_sizes, int n_in,
                              void* d_out, int out_size) {
  const float* data      = (const float*)d_in[0];
  const float* eps       = (const float*)d_in[1];
  const float* enc_Wih_f = (const float*)d_in[2];
  const float* enc_Whh_f = (const float*)d_in[3];
  const float* enc_b_f   = (const float*)d_in[4];
  const float* enc_Wih_b = (const float*)d_in[5];
  const float* enc_Whh_b = (const float*)d_in[6];
  const float* enc_b_b   = (const float*)d_in[7];
  const float* enc_out_W = (const float*)d_in[8];
  const float* enc_out_b = (const float*)d_in[9];
  const float* init_W    = (const float*)d_in[10];
  const float* init_b    = (const float*)d_in[11];
  const float* dec_Wih   = (const float*)d_in[12];
  const float* dec_Whh   = (const float*)d_in[13];
  const float* dec_b     = (const float*)d_in[14];
  const float* out_W     = (const float*)d_in[15];
  const float* out_b     = (const float*)d_in[16];
  const int*   lengths   = (const int*)d_in[17];

  float* out    = (float*)d_out;
  float* params = out;
  float* zm_out = out + (size_t)NB * NT * NOUTD;
  float* zl_out = zm_out + (size_t)NB * NT;

  cudaFuncSetAttribute(gemm3, cudaFuncAttributeMaxDynamicSharedMemorySize, GSMEM);

  __nv_bfloat16 *dWhh_hi, *dWhh_lo, *eWf_hi, *eWf_lo, *eWb_hi, *eWb_lo;
  __nv_bfloat16 *eOut_hi, *eOut_lo, *initW_hi, *initW_lo, *zW_hi, *zW_lo, *outW_hi, *outW_lo;
  __nv_bfloat16 *hn_hi, *hn_lo, *z_hi, *z_lo, *h0_hi, *h0_lo, *hs_hi, *hs_lo;
  float *Ge, *zml, *initb, *zp, *G;
  cudaGetSymbolAddress((void**)&dWhh_hi, g_dWhh_hi);
  cudaGetSymbolAddress((void**)&dWhh_lo, g_dWhh_lo);
  cudaGetSymbolAddress((void**)&eWf_hi, g_eWf_hi);
  cudaGetSymbolAddress((void**)&eWf_lo, g_eWf_lo);
  cudaGetSymbolAddress((void**)&eWb_hi, g_eWb_hi);
  cudaGetSymbolAddress((void**)&eWb_lo, g_eWb_lo);
  cudaGetSymbolAddress((void**)&eOut_hi, g_eOut_hi);
  cudaGetSymbolAddress((void**)&eOut_lo, g_eOut_lo);
  cudaGetSymbolAddress((void**)&initW_hi, g_initW_hi);
  cudaGetSymbolAddress((void**)&initW_lo, g_initW_lo);
  cudaGetSymbolAddress((void**)&zW_hi, g_zW_hi);
  cudaGetSymbolAddress((void**)&zW_lo, g_zW_lo);
  cudaGetSymbolAddress((void**)&outW_hi, g_outW_hi);
  cudaGetSymbolAddress((void**)&outW_lo, g_outW_lo);
  cudaGetSymbolAddress((void**)&hn_hi, g_hn_hi);
  cudaGetSymbolAddress((void**)&hn_lo, g_hn_lo);
  cudaGetSymbolAddress((void**)&z_hi, g_z_hi);
  cudaGetSymbolAddress((void**)&z_lo, g_z_lo);
  cudaGetSymbolAddress((void**)&h0_hi, g_h0_hi);
  cudaGetSymbolAddress((void**)&h0_lo, g_h0_lo);
  cudaGetSymbolAddress((void**)&hs_hi, g_hs_hi);
  cudaGetSymbolAddress((void**)&hs_lo, g_hs_lo);
  cudaGetSymbolAddress((void**)&Ge, g_Ge);
  cudaGetSymbolAddress((void**)&zml, g_zml);
  cudaGetSymbolAddress((void**)&initb, g_init);
  cudaGetSymbolAddress((void**)&zp, g_zp);
  cudaGetSymbolAddress((void**)&G, g_G);

  {
    long tot;
    tot = (long)NGD * NHD;
    cvt_kernel<<<(unsigned)((tot + 255) / 256), 256>>>(dec_Whh, NHD, NHD, dWhh_hi, dWhh_lo, tot);
    tot = (long)NGE * NHE;
    cvt_kernel<<<(unsigned)((tot + 255) / 256), 256>>>(enc_Whh_f, NHE, NHE, eWf_hi, eWf_lo, tot);
    cvt_kernel<<<(unsigned)((tot + 255) / 256), 256>>>(enc_Whh_b, NHE, NHE, eWb_hi, eWb_lo, tot);
    tot = (long)(2 * NZ) * (2 * NHE);
    cvt_kernel<<<(unsigned)((tot + 255) / 256), 256>>>(enc_out_W, 2 * NHE, 2 * NHE, eOut_hi, eOut_lo, tot);
    tot = (long)(2 * NHD) * NZ;
    cvt_kernel<<<(unsigned)((tot + 255) / 256), 256>>>(init_W, NZ, NZ, initW_hi, initW_lo, tot);
    tot = (long)NGD * NZ;
    cvt_kernel<<<(unsigned)((tot + 255) / 256), 256>>>(dec_Wih + 5, DLD, NZ, zW_hi, zW_lo, tot);
    tot = (long)NOUTD * NHD;
    cvt_kernel<<<(unsigned)((tot + 255) / 256), 256>>>(out_W, NHD, NHD, outW_hi, outW_lo, tot);
  }

  zero_init_kernel<<<2048, 256>>>();

  // ---- bidirectional encoder, 128 steps ----
  for (int t = 0; t < NT; t++) {
    GArg f = {hn_hi, hn_lo, eWf_hi, eWf_lo, enc_b_f, nullptr, Ge};
    GArg bw = {hn_hi + NHE, hn_lo + NHE, eWb_hi, eWb_lo, enc_b_b, nullptr, Ge + (size_t)NB * NGE};
    run_gemm(f, bw, 2 * NHE, NGE, NGE, NHE, NB, 2);
    enc_gate_kernel<<<2048, 256>>>(data, lengths, enc_Wih_f, enc_Wih_b, t);
  }

  // ---- latent ----
  {
    GArg a = {hn_hi, hn_lo, eOut_hi, eOut_lo, enc_out_b, nullptr, zml};
    run_gemm(a, a, 2 * NHE, 2 * NZ, 2 * NZ, 2 * NHE, NB, 1);
  }
  latent_kernel<<<256, 256>>>(eps, zm_out, zl_out);
  {
    GArg a = {z_hi, z_lo, initW_hi, initW_lo, init_b, nullptr, initb};
    run_gemm(a, a, NZ, 2 * NHD, 2 * NHD, NZ, NB, 1);
  }
  initsplit_kernel<<<4096, 256>>>();
  {
    GArg a = {z_hi, z_lo, zW_hi, zW_lo, dec_b, nullptr, zp};
    run_gemm(a, a, NZ, NGD, NGD, NZ, NB, 1);
  }

  // ---- decoder, 128 steps ----
  for (int t = 0; t < NT; t++) {
    const __nv_bfloat16* Ah = t ? (hs_hi + (size_t)(t - 1) * NHD) : h0_hi;
    const __nv_bfloat16* Al = t ? (hs_lo + (size_t)(t - 1) * NHD) : h0_lo;
    size_t lda = t ? (size_t)NT * NHD : (size_t)NHD;
    GArg a = {Ah, Al, dWhh_hi, dWhh_lo, nullptr, zp, G};
    run_gemm(a, a, lda, NGD, NGD, NHD, NB, 1);
    dec_gate_kernel<<<4096, 256>>>(data, dec_Wih, t);
  }

  // ---- output projection ----
  {
    GArg a = {hs_hi, hs_lo, outW_hi, outW_lo, out_b, nullptr, params};
    run_gemm(a, a, NHD, NOUTD, NOUTD, NHD, NB * NT, 1);
  }
}

// round 4
// speedup vs baseline: 6.3353x; 1.5543x over previous
#include <cuda_runtime.h>
#include <cuda_bf16.h>
#include <math.h>
#include <stdint.h>

#define NB 512
#define NT 128
#define NHE 512
#define NGE 2048
#define NZ 128
#define NHD 2048
#define NGD 8192
#define NOUTD 123
#define DATALD 129
#define DLD 133

// Use tcgen05 only when the compilation target is arch-specific sm_103a/100a.
#if !defined(__CUDA_ARCH__)
#define USE_TC 1   // host pass
#elif defined(__CUDA_ARCH_FEAT_SM103_ALL) || defined(__CUDA_ARCH_FEAT_SM100_ALL)
#define USE_TC 1
#else
#define USE_TC 0
#endif

// ---------------- device scratch ----------------
__device__ __nv_bfloat16 g_dWhh_hi[NGD * NHD];
__device__ __nv_bfloat16 g_dWhh_lo[NGD * NHD];
__device__ __nv_bfloat16 g_eWf_hi[NGE * NHE];
__device__ __nv_bfloat16 g_eWf_lo[NGE * NHE];
__device__ __nv_bfloat16 g_eWb_hi[NGE * NHE];
__device__ __nv_bfloat16 g_eWb_lo[NGE * NHE];
__device__ __nv_bfloat16 g_eOut_hi[2 * NZ * 2 * NHE];
__device__ __nv_bfloat16 g_eOut_lo[2 * NZ * 2 * NHE];
__device__ __nv_bfloat16 g_initW_hi[2 * NHD * NZ];
__device__ __nv_bfloat16 g_initW_lo[2 * NHD * NZ];
__device__ __nv_bfloat16 g_zW_hi[NGD * NZ];
__device__ __nv_bfloat16 g_zW_lo[NGD * NZ];
__device__ __nv_bfloat16 g_outW_hi[NOUTD * NHD];
__device__ __nv_bfloat16 g_outW_lo[NOUTD * NHD];

__device__ __nv_bfloat16 g_hn_hi[NB * 2 * NHE];
__device__ __nv_bfloat16 g_hn_lo[NB * 2 * NHE];
__device__ float g_ce[2 * NB * NHE];
__device__ float g_Ge[2 * NB * NGE];
__device__ float g_zml[NB * 2 * NZ];
__device__ __nv_bfloat16 g_z_hi[NB * NZ];
__device__ __nv_bfloat16 g_z_lo[NB * NZ];
__device__ float g_init[NB * 2 * NHD];
__device__ __nv_bfloat16 g_h0_hi[NB * NHD];
__device__ __nv_bfloat16 g_h0_lo[NB * NHD];
__device__ float g_cd[NB * NHD];
__device__ float g_zp[NB * NGD];
__device__ float g_G[NB * NGD];
__device__ __nv_bfloat16 g_hs_hi[(size_t)NB * NT * NHD];
__device__ __nv_bfloat16 g_hs_lo[(size_t)NB * NT * NHD];

// ---------------- common helpers ----------------
__device__ __forceinline__ uint32_t smem_u32(const void* p) {
  uint32_t a;
  asm("{ .reg .u64 t; cvta.to.shared.u64 t, %1; cvt.u32.u64 %0, t; }" : "=r"(a) : "l"(p));
  return a;
}
__device__ __forceinline__ void cp16(uint32_t dst, const void* src, bool ok) {
  int sz = ok ? 16 : 0;
  asm volatile("cp.async.cg.shared.global [%0], [%1], 16, %2;\n"
               :: "r"(dst), "l"(src), "r"(sz) : "memory");
}
__device__ __forceinline__ void cp_commit() { asm volatile("cp.async.commit_group;" ::: "memory"); }
__device__ __forceinline__ void cp_wait1()  { asm volatile("cp.async.wait_group 1;" ::: "memory"); }
__device__ __forceinline__ void cp_wait0()  { asm volatile("cp.async.wait_group 0;" ::: "memory"); }

struct GArg {
  const __nv_bfloat16 *Ahi, *Alo;      // [M][K] fp32-split, row stride lda
  const __nv_bfloat16 *Whi, *Wlo;      // [N][K] packed (ldw == K)
  const float *bias;                   // [N] or null
  const float *Cadd;                   // [M][ldc] addend or null
  float *C;                            // [M][ldc]
};

#define STAGE_BYTES 98304u
#define GSMEM (1024u + 2u * STAGE_BYTES)

#if USE_TC
// =====================================================================
// tcgen05 path (arch-specific sm_103a/100a targets only)
// =====================================================================
__device__ __forceinline__ uint32_t elect_one_pred() {
  uint32_t pred;
  asm volatile(
      "{\n\t.reg .pred p;\n\telect.sync _|p, 0xFFFFFFFF;\n\tselp.b32 %0, 1, 0, p;\n\t}"
      : "=r"(pred));
  return pred;
}
#define MBARRIER_INIT(addr, cnt) \
  asm volatile("mbarrier.init.shared.b64 [%0], %1;" :: "r"((uint32_t)(addr)), "r"((uint32_t)(cnt)) : "memory")
#define MBARRIER_WAIT_PARITY(addr, par) do {                                        \
  uint32_t _m = (uint32_t)(addr); uint32_t _p = (uint32_t)(par); uint32_t _d;       \
  asm volatile("{\n\t.reg .pred p;\n\t"                                             \
    "mbarrier.try_wait.parity.acquire.cta.shared::cta.b64 p, [%1], %2;\n\t"         \
    "selp.b32 %0, 1, 0, p;\n\t}" : "=r"(_d) : "r"(_m), "r"(_p) : "memory");         \
  if (!_d) {                                                                        \
    asm volatile("{\n\t.reg .pred P1;\n\t"                                          \
      "WL_%=:\n\t"                                                                  \
      "mbarrier.try_wait.parity.acquire.cta.shared::cta.b64 P1, [%0], %1, 0x989680;\n\t" \
      "@P1 bra.uni WD_%=;\n\t"                                                      \
      "bra.uni WL_%=;\n\t"                                                          \
      "WD_%=:\n\t}" :: "r"(_m), "r"(_p) : "memory");                                \
  }                                                                                 \
} while (0)

#define TCGEN05_ALLOC(sm, n) \
  asm volatile("tcgen05.alloc.cta_group::1.sync.aligned.shared::cta.b32 [%0], %1;" \
               :: "r"((uint32_t)(sm)), "r"((uint32_t)(n)) : "memory")
#define TCGEN05_DEALLOC(t, n) \
  asm volatile("tcgen05.dealloc.cta_group::1.sync.aligned.b32 %0, %1;" :: "r"(t), "r"((uint32_t)(n)))
#define TCGEN05_RELINQ() \
  asm volatile("tcgen05.relinquish_alloc_permit.cta_group::1.sync.aligned;")
#define TCGEN05_COMMIT(mb) \
  asm volatile("tcgen05.commit.cta_group::1.mbarrier::arrive::one.shared::cluster.b64 [%0];" \
               :: "r"((uint32_t)(mb)) : "memory")
#define TCGEN05_FENCE_AFTER()  asm volatile("tcgen05.fence::after_thread_sync;" ::: "memory")
#define TCGEN05_FENCE_BEFORE() asm volatile("tcgen05.fence::before_thread_sync;" ::: "memory")
#define TCGEN05_WAIT_LD()      asm volatile("tcgen05.wait::ld.sync.aligned;" ::: "memory")

#define TCGEN05_LD_32X32B_X32(r, addr)                                            \
  asm volatile(                                                                   \
      "tcgen05.ld.sync.aligned.32x32b.x32.b32 "                                   \
      "{%0, %1, %2, %3, %4, %5, %6, %7, %8, %9, %10, %11, %12, %13, %14, %15, "   \
      " %16, %17, %18, %19, %20, %21, %22, %23, %24, %25, %26, %27, %28, %29, %30, %31}, [%32];" \
      : "=r"((r)[0]), "=r"((r)[1]), "=r"((r)[2]), "=r"((r)[3]),                   \
        "=r"((r)[4]), "=r"((r)[5]), "=r"((r)[6]), "=r"((r)[7]),                   \
        "=r"((r)[8]), "=r"((r)[9]), "=r"((r)[10]), "=r"((r)[11]),                 \
        "=r"((r)[12]), "=r"((r)[13]), "=r"((r)[14]), "=r"((r)[15]),               \
        "=r"((r)[16]), "=r"((r)[17]), "=r"((r)[18]), "=r"((r)[19]),               \
        "=r"((r)[20]), "=r"((r)[21]), "=r"((r)[22]), "=r"((r)[23]),               \
        "=r"((r)[24]), "=r"((r)[25]), "=r"((r)[26]), "=r"((r)[27]),               \
        "=r"((r)[28]), "=r"((r)[29]), "=r"((r)[30]), "=r"((r)[31])                \
      : "r"(addr))

static constexpr unsigned long long SMEM_DESC_BASE_SW128 =
    (2ull << 61) | (1ull << 46) | (64ull << 32) | (1ull << 16);
#define MAKE_SMEM_DESC(a) (SMEM_DESC_BASE_SW128 | ((unsigned long long)((a) >> 4) & 0x3FFF))

static constexpr uint32_t IDESC =
    (1u << 4) | (1u << 7) | (1u << 10) | ((256u / 8u) << 17) | ((128u / 16u) << 24);

__device__ __forceinline__ void mma_ss(uint32_t d, unsigned long long a,
                                       unsigned long long b, uint32_t en) {
  asm volatile(
      "{\n\t.reg .pred p;\n\tsetp.ne.u32 p, %4, 0;\n\t"
      "tcgen05.mma.cta_group::1.kind::f16 [%0], %1, %2, %3, {%5, %5, %5, %5}, p;\n\t}"
      :: "r"(d), "l"(a), "l"(b), "r"(IDESC), "r"(en), "r"(0u) : "memory");
}

__device__ __forceinline__ void load_stage(
    uint32_t sb, int stage, int ci, const GArg& g, size_t lda,
    int m0, int n0, int N, int K, int tid)
{
  const uint32_t base = sb + 1024u + (uint32_t)stage * STAGE_BYTES;
  const int k0 = ci << 6;
#pragma unroll
  for (int it = 0; it < 4; ++it) {
    int idx = tid + (it << 8);
    int row = idx >> 3, c = idx & 7;
    uint32_t off = (uint32_t)((row << 7) + (c << 4));
    off ^= ((off >> 3) & 0x70);
    size_t so = (size_t)(m0 + row) * lda + (size_t)k0 + (c << 3);
    cp16(base + off, g.Ahi + so, true);
    cp16(base + 16384u + off, g.Alo + so, true);
  }
#pragma unroll
  for (int it = 0; it < 8; ++it) {
    int idx = tid + (it << 8);
    int row = idx >> 3, c = idx & 7;
    int n = n0 + row;
    bool ok = (n < N);
    size_t so = (size_t)(ok ? n : 0) * (size_t)K + (size_t)k0 + (c << 3);
    uint32_t off = (uint32_t)((row << 7) + (c << 4));
    off ^= ((off >> 3) & 0x70);
    cp16(base + 32768u + off, g.Whi + so, ok);
    cp16(base + 65536u + off, g.Wlo + so, ok);
  }
  cp_commit();
}

__device__ __forceinline__ void mma_chunk(uint32_t sb, int stage, uint32_t tmem, bool first) {
  uint32_t base = sb + 1024u + (uint32_t)stage * STAGE_BYTES;
  unsigned long long dAh = MAKE_SMEM_DESC(base);
  unsigned long long dAl = MAKE_SMEM_DESC(base + 16384u);
  unsigned long long dBh = MAKE_SMEM_DESC(base + 32768u);
  unsigned long long dBl = MAKE_SMEM_DESC(base + 65536u);
#pragma unroll
  for (int ks = 0; ks < 4; ++ks) {
    unsigned long long o = (unsigned long long)(2 * ks);
    mma_ss(tmem, dAh + o, dBh + o, (first && ks == 0) ? 0u : 1u);
    mma_ss(tmem, dAh + o, dBl + o, 1u);
    mma_ss(tmem, dAl + o, dBh + o, 1u);
  }
}

__global__ void __launch_bounds__(256, 1) gemm3(GArg a0, GArg a1, size_t lda,
                                                size_t ldc, int N, int K) {
  extern __shared__ __align__(1024) char smem[];
  const int tid = threadIdx.x;
  const uint32_t sb = smem_u32(smem);
  const GArg g = blockIdx.z ? a1 : a0;
  const int m0 = blockIdx.y * 128;
  const int n0 = blockIdx.x * 256;

  if (tid == 0) { MBARRIER_INIT(sb + 16, 1); MBARRIER_INIT(sb + 24, 1); }
  if (tid < 32) TCGEN05_ALLOC(sb, 256);
  __syncthreads();
  uint32_t tmem;
  asm volatile("ld.shared.b32 %0, [%1];" : "=r"(tmem) : "r"(sb));

  const int nch = K >> 6;
  load_stage(sb, 0, 0, g, lda, m0, n0, N, K, tid);
  load_stage(sb, 1, 1, g, lda, m0, n0, N, K, tid);

  for (int i = 0; i < nch; ++i) {
    const int b = i & 1;
    if (i + 1 < nch) cp_wait1(); else cp_wait0();
    asm volatile("fence.proxy.async.shared::cta;" ::: "memory");
    __syncthreads();
    if (tid < 32) {
      if (elect_one_pred()) {
        mma_chunk(sb, b, tmem, i == 0);
        TCGEN05_COMMIT(sb + 16 + 8 * b);
      }
    }
    if (i + 2 < nch) {
      MBARRIER_WAIT_PARITY(sb + 16 + 8 * b, (i >> 1) & 1);
      load_stage(sb, b, i + 2, g, lda, m0, n0, N, K, tid);
    }
  }
  const int last = nch - 1;
  MBARRIER_WAIT_PARITY(sb + 16 + 8 * (last & 1), (last >> 1) & 1);
  TCGEN05_FENCE_AFTER();

  if (tid < 128) {
    const int w = tid >> 5, lane = tid & 31;
    const size_t m = (size_t)m0 + (size_t)(w * 32 + lane);
    float* crow = g.C + m * ldc;
    const float* arow = g.Cadd ? (g.Cadd + m * ldc) : (const float*)0;
    for (int c0 = 0; c0 < 256; c0 += 32) {
      int n = n0 + c0;
      if (n >= N) break;
      uint32_t r[32];
      TCGEN05_LD_32X32B_X32(r, tmem + c0);
      TCGEN05_WAIT_LD();
      if (((ldc & 3) == 0) && (n + 32 <= N)) {
#pragma unroll
        for (int q = 0; q < 8; ++q) {
          float4 v;
          v.x = __uint_as_float(r[4 * q + 0]);
          v.y = __uint_as_float(r[4 * q + 1]);
          v.z = __uint_as_float(r[4 * q + 2]);
          v.w = __uint_as_float(r[4 * q + 3]);
          if (g.bias) {
            float4 bv = *(const float4*)(g.bias + n + 4 * q);
            v.x += bv.x; v.y += bv.y; v.z += bv.z; v.w += bv.w;
          }
          if (arow) {
            float4 av = *(const float4*)(arow + n + 4 * q);
            v.x += av.x; v.y += av.y; v.z += av.z; v.w += av.w;
          }
          *(float4*)(crow + n + 4 * q) = v;
        }
      } else {
        for (int j = 0; j < 32 && n + j < N; ++j) {
          float v = __uint_as_float(r[j]);
          if (g.bias) v += g.bias[n + j];
          if (arow) v += arow[n + j];
          crow[n + j] = v;
        }
      }
    }
    TCGEN05_FENCE_BEFORE();
  }
  __syncthreads();
  if (tid < 32) { TCGEN05_RELINQ(); TCGEN05_DEALLOC(tmem, 256); }
}

#else
// =====================================================================
// Fallback: mma.sync m16n8k16 bf16 with ldmatrix fragment loads.
// CTA tile 128x256 as two 128x128 halves; hi/lo 3-term split.
// =====================================================================
#define KC 64
#define FSTAGE 65536u

__device__ __forceinline__ void ldsm4(uint32_t& r0, uint32_t& r1, uint32_t& r2,
                                      uint32_t& r3, uint32_t addr) {
  asm volatile("ldmatrix.sync.aligned.m8n8.x4.shared.b16 {%0,%1,%2,%3}, [%4];"
               : "=r"(r0), "=r"(r1), "=r"(r2), "=r"(r3) : "r"(addr));
}
__device__ __forceinline__ void mma16816(float* c, uint32_t a0, uint32_t a1,
                                         uint32_t a2, uint32_t a3,
                                         uint32_t b0, uint32_t b1) {
  asm volatile(
      "mma.sync.aligned.m16n8k16.row.col.f32.bf16.bf16.f32 "
      "{%0,%1,%2,%3}, {%4,%5,%6,%7}, {%8,%9}, {%0,%1,%2,%3};"
      : "+f"(c[0]), "+f"(c[1]), "+f"(c[2]), "+f"(c[3])
      : "r"(a0), "r"(a1), "r"(a2), "r"(a3), "r"(b0), "r"(b1));
}

__device__ __forceinline__ void f_load_stage(
    uint32_t sb, int stage, int ci, int hf, const GArg& g, size_t lda,
    int m0, int n0, int N, int K, int tid)
{
  const uint32_t base = sb + (uint32_t)stage * FSTAGE;
  const int k0 = ci * KC;
#pragma unroll
  for (int it = 0; it < 4; ++it) {
    int idx = tid + (it << 8);
    int row = idx >> 3, c = idx & 7;
    uint32_t off = (uint32_t)((row << 7) + (c << 4));
    off ^= (off >> 3) & 0x70;
    size_t soA = (size_t)(m0 + row) * lda + (size_t)k0 + (c << 3);
    cp16(base + off, g.Ahi + soA, true);
    cp16(base + 16384u + off, g.Alo + soA, true);
    int n = n0 + hf * 128 + row;
    bool ok = (n < N);
    size_t soB = (size_t)(ok ? n : 0) * (size_t)K + (size_t)k0 + (c << 3);
    cp16(base + 32768u + off, g.Whi + soB, ok);
    cp16(base + 49152u + off, g.Wlo + soB, ok);
  }
  cp_commit();
}

__global__ void __launch_bounds__(256, 1) gemm3(GArg a0, GArg a1, size_t lda,
                                                size_t ldc, int N, int K) {
  extern __shared__ __align__(1024) char smem[];
  const int tid = threadIdx.x;
  const uint32_t sb = smem_u32(smem);
  const GArg g = blockIdx.z ? a1 : a0;
  const int m0 = blockIdx.y * 128;
  const int n0 = blockIdx.x * 256;
  const int w = tid >> 5, l = tid & 31;
  const int r = l >> 2, c2 = (l & 3) << 1;
  const int nch = K / KC;

  // per-lane ldmatrix address components (swizzle reduces to fixed XOR)
  const uint32_t l7 = (uint32_t)(l & 7);
  const uint32_t xm = l7 << 4;                           // row%8 XOR mask
  const uint32_t a_rowb = (uint32_t)((w * 16 + (l & 15)) << 7);
  const uint32_t a_kh = (uint32_t)((l >> 4) << 4);       // 0 or 16 bytes
  const uint32_t b_rowb = (uint32_t)((((l >> 4) << 3) + (int)l7) << 7);
  const uint32_t b_kh = (uint32_t)(((l >> 3) & 1) << 4);

  for (int hf = 0; hf < 2; ++hf) {
    if (n0 + hf * 128 >= N) break;
    float acc[16][4];
#pragma unroll
    for (int i = 0; i < 16; ++i)
#pragma unroll
      for (int j = 0; j < 4; ++j) acc[i][j] = 0.0f;

    f_load_stage(sb, 0, 0, hf, g, lda, m0, n0, N, K, tid);
    f_load_stage(sb, 1, 1, hf, g, lda, m0, n0, N, K, tid);

    for (int ci = 0; ci < nch; ++ci) {
      const int b = ci & 1;
      if (ci + 1 < nch) cp_wait1(); else cp_wait0();
      __syncthreads();
      const uint32_t Ah = sb + (uint32_t)b * FSTAGE;
      const uint32_t Al = Ah + 16384u;
      const uint32_t Bh = Ah + 32768u;
      const uint32_t Bl = Ah + 49152u;
#pragma unroll
      for (int ks = 0; ks < 4; ++ks) {
        const uint32_t akOff = (((uint32_t)(32 * ks) + a_kh) ^ xm);
        const uint32_t bkOff = (((uint32_t)(32 * ks) + b_kh) ^ xm);
        uint32_t ah0, ah1, ah2, ah3, al0, al1, al2, al3;
        ldsm4(ah0, ah1, ah2, ah3, Ah + a_rowb + akOff);
        ldsm4(al0, al1, al2, al3, Al + a_rowb + akOff);
#pragma unroll
        for (int np = 0; np < 8; ++np) {
          const uint32_t baddr = b_rowb + (uint32_t)(np << 11) + bkOff;
          uint32_t bh0, bh1, bh2, bh3, bl0, bl1, bl2, bl3;
          ldsm4(bh0, bh1, bh2, bh3, Bh + baddr);
          ldsm4(bl0, bl1, bl2, bl3, Bl + baddr);
          mma16816(acc[2 * np],     ah0, ah1, ah2, ah3, bh0, bh1);
          mma16816(acc[2 * np],     ah0, ah1, ah2, ah3, bl0, bl1);
          mma16816(acc[2 * np],     al0, al1, al2, al3, bh0, bh1);
          mma16816(acc[2 * np + 1], ah0, ah1, ah2, ah3, bh2, bh3);
          mma16816(acc[2 * np + 1], ah0, ah1, ah2, ah3, bl2, bl3);
          mma16816(acc[2 * np + 1], al0, al1, al2, al3, bh2, bh3);
        }
      }
      __syncthreads();
      if (ci + 2 < nch) f_load_stage(sb, b, ci + 2, hf, g, lda, m0, n0, N, K, tid);
    }

    const int mtop = m0 + w * 16 + r;
#pragma unroll
    for (int nb = 0; nb < 16; ++nb) {
      int n = n0 + hf * 128 + nb * 8 + c2;
#pragma unroll
      for (int half = 0; half < 2; ++half) {
        int m = mtop + half * 8;
        float v0 = acc[nb][2 * half], v1 = acc[nb][2 * half + 1];
        if (g.bias) { v0 += g.bias[n < N ? n : 0]; v1 += (n + 1 < N) ? g.bias[n + 1] : 0.0f; }
        if (g.Cadd) {
          const float* arow = g.Cadd + (size_t)m * ldc;
          if (n < N) v0 += arow[n];
          if (n + 1 < N) v1 += arow[n + 1];
        }
        float* crow = g.C + (size_t)m * ldc;
        if (n < N) crow[n] = v0;
        if (n + 1 < N) crow[n + 1] = v1;
      }
    }
  }
}
#endif  // USE_TC

// ---------------- small kernels ----------------
__device__ __forceinline__ float sigf(float x) { return 1.0f / (1.0f + expf(-x)); }
__device__ __forceinline__ void split_bf16(float x, __nv_bfloat16* hi, __nv_bfloat16* lo) {
  __nv_bfloat16 h = __float2bfloat16(x);
  *hi = h;
  *lo = __float2bfloat16(x - __bfloat162float(h));
}

// single merged conversion + zero-init kernel (keeps launch #5 = gemm3)
#define SEG0 16777216L                 // dWhh 8192*2048
#define SEG1 (SEG0 + 1048576L)         // eWf 2048*512
#define SEG2 (SEG1 + 1048576L)         // eWb   (note: 2048*512 = 1048576)
#define SEG3 (SEG2 + 262144L)          // eOut 256*1024
#define SEG4 (SEG3 + 524288L)          // initW 4096*128
#define SEG5 (SEG4 + 1048576L)         // zW 8192*128
#define SEG6 (SEG5 + 251904L)          // outW 123*2048
#define SEG7 (SEG6 + 524288L)          // hn/ce zero init
__global__ void cvt_all(const float* __restrict__ dWhh, const float* __restrict__ eWf,
                        const float* __restrict__ eWb, const float* __restrict__ eOut,
                        const float* __restrict__ initW, const float* __restrict__ decWih,
                        const float* __restrict__ outW) {
  long idx = blockIdx.x * 256L + threadIdx.x;
  if (idx >= SEG7) return;
  if (idx < SEG0) {
    split_bf16(dWhh[idx], &g_dWhh_hi[idx], &g_dWhh_lo[idx]);
  } else if (idx < SEG1) {
    long i = idx - SEG0; split_bf16(eWf[i], &g_eWf_hi[i], &g_eWf_lo[i]);
  } else if (idx < SEG2) {
    long i = idx - SEG1; split_bf16(eWb[i], &g_eWb_hi[i], &g_eWb_lo[i]);
  } else if (idx < SEG3) {
    long i = idx - SEG2; split_bf16(eOut[i], &g_eOut_hi[i], &g_eOut_lo[i]);
  } else if (idx < SEG4) {
    long i = idx - SEG3; split_bf16(initW[i], &g_initW_hi[i], &g_initW_lo[i]);
  } else if (idx < SEG5) {
    long i = idx - SEG4;
    long n = i >> 7, k = i & 127;
    split_bf16(decWih[n * DLD + 5 + k], &g_zW_hi[i], &g_zW_lo[i]);
  } else if (idx < SEG6) {
    long i = idx - SEG5; split_bf16(outW[i], &g_outW_hi[i], &g_outW_lo[i]);
  } else {
    long i = idx - SEG6;
    g_hn_hi[i] = __float2bfloat16(0.0f);
    g_hn_lo[i] = __float2bfloat16(0.0f);
    g_ce[i] = 0.0f;
  }
}

__global__ void enc_gate_kernel(const float* __restrict__ data,
                                const int* __restrict__ lengths,
                                const float* __restrict__ Wih_f,
                                const float* __restrict__ Wih_b, int t) {
  int idx = blockIdx.x * blockDim.x + threadIdx.x;
  int dir = idx >> 18;
  int rr = idx & ((1 << 18) - 1);
  int b = rr >> 9;
  int j = rr & 511;
  int L = lengths[b];
  L = L < 1 ? 1 : (L > NT ? NT : L);
  if (t >= L) return;
  int ti = dir ? (L - 1 - t) : t;
  float x0 = data[((size_t)b * DATALD + ti + 1) * 2 + 0];
  float x1 = data[((size_t)b * DATALD + ti + 1) * 2 + 1];
  const float* Wih = dir ? Wih_b : Wih_f;
  const float* G = g_Ge + (size_t)(dir * NB + b) * NGE;
  float pi = G[j]           + x0 * Wih[2 * j]               + x1 * Wih[2 * j + 1];
  float pf = G[NHE + j]     + x0 * Wih[2 * (NHE + j)]       + x1 * Wih[2 * (NHE + j) + 1];
  float pg = G[2 * NHE + j] + x0 * Wih[2 * (2 * NHE + j)]   + x1 * Wih[2 * (2 * NHE + j) + 1];
  float po = G[3 * NHE + j] + x0 * Wih[2 * (3 * NHE + j)]   + x1 * Wih[2 * (3 * NHE + j) + 1];
  int ci = (dir * NB + b) * NHE + j;
  float c = g_ce[ci];
  float c2 = sigf(pf) * c + sigf(pi) * tanhf(pg);
  float h2 = sigf(po) * tanhf(c2);
  g_ce[ci] = c2;
  int hidx = b * (2 * NHE) + dir * NHE + j;
  split_bf16(h2, &g_hn_hi[hidx], &g_hn_lo[hidx]);
}

__global__ void latent_kernel(const float* __restrict__ eps,
                              float* __restrict__ zm_out,
                              float* __restrict__ zl_out) {
  int idx = blockIdx.x * blockDim.x + threadIdx.x;
  int b = idx >> 7, k = idx & 127;
  float zm = g_zml[b * 256 + k];
  float zl = g_zml[b * 256 + 128 + k];
  zm_out[idx] = zm;
  zl_out[idx] = zl;
  float z = zm + expf(0.5f * zl) * eps[idx];
  split_bf16(z, &g_z_hi[idx], &g_z_lo[idx]);
}

__global__ void initsplit_kernel() {
  int idx = blockIdx.x * blockDim.x + threadIdx.x;
  int b = idx >> 11, j = idx & 2047;
  float h0 = tanhf(g_init[b * (2 * NHD) + j]);
  float c0 = tanhf(g_init[b * (2 * NHD) + NHD + j]);
  g_cd[idx] = c0;
  split_bf16(h0, &g_h0_hi[idx], &g_h0_lo[idx]);
}

__global__ void dec_gate_kernel(const float* __restrict__ data,
                                const float* __restrict__ Wih, int t) {
  int idx = blockIdx.x * blockDim.x + threadIdx.x;
  int b = idx >> 11, j = idx & 2047;
  float x0 = data[((size_t)b * DATALD + t) * 2 + 0];
  float x1 = data[((size_t)b * DATALD + t) * 2 + 1];
  const float* G = g_G + (size_t)b * NGD;
  int r0 = j, r1 = j + NHD, r2 = j + 2 * NHD, r3 = j + 3 * NHD;
  float pi = G[r0] + x0 * Wih[(size_t)r0 * DLD] + x1 * Wih[(size_t)r0 * DLD + 1];
  float pf = G[r1] + x0 * Wih[(size_t)r1 * DLD] + x1 * Wih[(size_t)r1 * DLD + 1];
  float pg = G[r2] + x0 * Wih[(size_t)r2 * DLD] + x1 * Wih[(size_t)r2 * DLD + 1];
  float po = G[r3] + x0 * Wih[(size_t)r3 * DLD] + x1 * Wih[(size_t)r3 * DLD + 1];
  float c = g_cd[idx];
  float c2 = sigf(pf) * c + sigf(pi) * tanhf(pg);
  float h2 = sigf(po) * tanhf(c2);
  g_cd[idx] = c2;
  size_t ho = ((size_t)b * NT + t) * NHD + j;
  split_bf16(h2, &g_hs_hi[ho], &g_hs_lo[ho]);
}

// ---------------- launch ----------------
static inline void run_gemm(GArg a0, GArg a1, size_t lda, size_t ldc, int N, int K,
                            int M, int nz) {
  dim3 grid((unsigned)((N + 255) / 256), (unsigned)(M / 128), (unsigned)nz);
  gemm3<<<grid, 256, GSMEM>>>(a0, a1, lda, ldc, N, K);
}

extern "C" void kernel_launch(void* const* d_in, const int* in_sizes, int n_in,
                              void* d_out, int out_size) {
  const float* data      = (const float*)d_in[0];
  const float* eps       = (const float*)d_in[1];
  const float* enc_Wih_f = (const float*)d_in[2];
  const float* enc_Whh_f = (const float*)d_in[3];
  const float* enc_b_f   = (const float*)d_in[4];
  const float* enc_Wih_b = (const float*)d_in[5];
  const float* enc_Whh_b = (const float*)d_in[6];
  const float* enc_b_b   = (const float*)d_in[7];
  const float* enc_out_W = (const float*)d_in[8];
  const float* enc_out_b = (const float*)d_in[9];
  const float* init_W    = (const float*)d_in[10];
  const float* init_b    = (const float*)d_in[11];
  const float* dec_Wih   = (const float*)d_in[12];
  const float* dec_Whh   = (const float*)d_in[13];
  const float* dec_b     = (const float*)d_in[14];
  const float* out_W     = (const float*)d_in[15];
  const float* out_b     = (const float*)d_in[16];
  const int*   lengths   = (const int*)d_in[17];

  float* out    = (float*)d_out;
  float* params = out;
  float* zm_out = out + (size_t)NB * NT * NOUTD;
  float* zl_out = zm_out + (size_t)NB * NT;

  cudaFuncSetAttribute(gemm3, cudaFuncAttributeMaxDynamicSharedMemorySize, GSMEM);

  __nv_bfloat16 *dWhh_hi, *dWhh_lo, *eWf_hi, *eWf_lo, *eWb_hi, *eWb_lo;
  __nv_bfloat16 *eOut_hi, *eOut_lo, *initW_hi, *initW_lo, *zW_hi, *zW_lo, *outW_hi, *outW_lo;
  __nv_bfloat16 *hn_hi, *hn_lo, *z_hi, *z_lo, *h0_hi, *h0_lo, *hs_hi, *hs_lo;
  float *Ge, *zml, *initb, *zp, *G;
  cudaGetSymbolAddress((void**)&dWhh_hi, g_dWhh_hi);
  cudaGetSymbolAddress((void**)&dWhh_lo, g_dWhh_lo);
  cudaGetSymbolAddress((void**)&eWf_hi, g_eWf_hi);
  cudaGetSymbolAddress((void**)&eWf_lo, g_eWf_lo);
  cudaGetSymbolAddress((void**)&eWb_hi, g_eWb_hi);
  cudaGetSymbolAddress((void**)&eWb_lo, g_eWb_lo);
  cudaGetSymbolAddress((void**)&eOut_hi, g_eOut_hi);
  cudaGetSymbolAddress((void**)&eOut_lo, g_eOut_lo);
  cudaGetSymbolAddress((void**)&initW_hi, g_initW_hi);
  cudaGetSymbolAddress((void**)&initW_lo, g_initW_lo);
  cudaGetSymbolAddress((void**)&zW_hi, g_zW_hi);
  cudaGetSymbolAddress((void**)&zW_lo, g_zW_lo);
  cudaGetSymbolAddress((void**)&outW_hi, g_outW_hi);
  cudaGetSymbolAddress((void**)&outW_lo, g_outW_lo);
  cudaGetSymbolAddress((void**)&hn_hi, g_hn_hi);
  cudaGetSymbolAddress((void**)&hn_lo, g_hn_lo);
  cudaGetSymbolAddress((void**)&z_hi, g_z_hi);
  cudaGetSymbolAddress((void**)&z_lo, g_z_lo);
  cudaGetSymbolAddress((void**)&h0_hi, g_h0_hi);
  cudaGetSymbolAddress((void**)&h0_lo, g_h0_lo);
  cudaGetSymbolAddress((void**)&hs_hi, g_hs_hi);
  cudaGetSymbolAddress((void**)&hs_lo, g_hs_lo);
  cudaGetSymbolAddress((void**)&Ge, g_Ge);
  cudaGetSymbolAddress((void**)&zml, g_zml);
  cudaGetSymbolAddress((void**)&initb, g_init);
  cudaGetSymbolAddress((void**)&zp, g_zp);
  cudaGetSymbolAddress((void**)&G, g_G);

  // launch 0: all weight conversions + state zero-init in ONE kernel
  cvt_all<<<(unsigned)((SEG7 + 255) / 256), 256>>>(
      dec_Whh, enc_Whh_f, enc_Whh_b, enc_out_W, init_W, dec_Wih, out_W);

  // ---- bidirectional encoder, 128 steps (launches 1..256) ----
  for (int t = 0; t < NT; t++) {
    GArg f = {hn_hi, hn_lo, eWf_hi, eWf_lo, enc_b_f, nullptr, Ge};
    GArg bw = {hn_hi + NHE, hn_lo + NHE, eWb_hi, eWb_lo, enc_b_b, nullptr, Ge + (size_t)NB * NGE};
    run_gemm(f, bw, 2 * NHE, NGE, NGE, NHE, NB, 2);
    enc_gate_kernel<<<2048, 256>>>(data, lengths, enc_Wih_f, enc_Wih_b, t);
  }

  // ---- latent ----
  {
    GArg a = {hn_hi, hn_lo, eOut_hi, eOut_lo, enc_out_b, nullptr, zml};
    run_gemm(a, a, 2 * NHE, 2 * NZ, 2 * NZ, 2 * NHE, NB, 1);
  }
  latent_kernel<<<256, 256>>>(eps, zm_out, zl_out);
  {
    GArg a = {z_hi, z_lo, initW_hi, initW_lo, init_b, nullptr, initb};
    run_gemm(a, a, NZ, 2 * NHD, 2 * NHD, NZ, NB, 1);
  }
  initsplit_kernel<<<4096, 256>>>();
  {
    GArg a = {z_hi, z_lo, zW_hi, zW_lo, dec_b, nullptr, zp};
    run_gemm(a, a, NZ, NGD, NGD, NZ, NB, 1);
  }

  // ---- decoder, 128 steps ----
  for (int t = 0; t < NT; t++) {
    const __nv_bfloat16* Ah = t ? (hs_hi + (size_t)(t - 1) * NHD) : h0_hi;
    const __nv_bfloat16* Al = t ? (hs_lo + (size_t)(t - 1) * NHD) : h0_lo;
    size_t lda = t ? (size_t)NT * NHD : (size_t)NHD;
    GArg a = {Ah, Al, dWhh_hi, dWhh_lo, nullptr, zp, G};
    run_gemm(a, a, lda, NGD, NGD, NHD, NB, 1);
    dec_gate_kernel<<<4096, 256>>>(data, dec_Wih, t);
  }

  // ---- output projection ----
  {
    GArg a = {hs_hi, hs_lo, outW_hi, outW_lo, out_b, nullptr, params};
    run_gemm(a, a, NHD, NOUTD, NOUTD, NHD, NB * NT, 1);
  }
}